// round 6
// baseline (speedup 1.0000x reference)
#include <cuda_runtime.h>
#include <math.h>

#define Bb 16
#define Tt 12
#define Nn 300
#define Dd 64
#define T2 10
#define BT (Bb*Tt)        // 192
#define BW (Bb*T2)        // 160
#define QPAD 68           // padded row stride for transposed tiles (multiple of 4!)

// Scratch (static device allocations; no cudaMalloc allowed)
__device__ float g_S5[BT*5*Dd*Dd];     // partial S = sum_n scale_n f f^T per (bt,chunk)
__device__ float g_ss5[BT*5*Dd];       // partial ss = sum_n scale_n f[n,:]
__device__ float g_G[BW*Dd*Dd];        // per-window diag(sw^2) S_win w1
__device__ float g_v[BW*Dd];           // per-window sw^2 * ss_win

// ---------------------------------------------------------------------------
// Kernel A: per (bt, chunk of 64 rows): scale_n = 1/max(||f_n .* sw||,eps),
//   partial S[j,d] = sum_n scale_n f[n,j] f[n,d], partial ss[j].
// 256 threads = 2 n-halves x (16 j-groups x 8 d-groups), thread tile 4x8.
// ---------------------------------------------------------------------------
__global__ __launch_bounds__(256) void kA(const float* __restrict__ feat,
                                          const float* __restrict__ weights) {
    __shared__ float sw[Dd];
    __shared__ float fs[64][Dd];
    __shared__ float scs[64];
    __shared__ float red[128][33];   // half-1 partials (pad 33: conflict-free)
    __shared__ float sks[64];        // half-1 column-sum partials
    const int blk = blockIdx.x;
    const int bt  = blk / 5;
    const int c   = blk % 5;
    const int r0  = c * 64;
    const int nr  = min(64, Nn - r0);     // 64 or 44
    const int tid = threadIdx.x;
    if (tid < Dd) sw[tid] = 1.0f / (1.0f + expf(-weights[tid]));

    const float* fbase = feat + ((size_t)bt * Nn + r0) * Dd;
    const int nv = nr * 16;
    for (int i = tid; i < nv; i += 256)
        ((float4*)fs)[i] = ((const float4*)fbase)[i];
    __syncthreads();

    // per-row scale (4 threads/row) + zero-pad invalid rows
    {
        const int row = tid >> 2, part = tid & 3;
        float s = 0.0f;
        #pragma unroll
        for (int k = 0; k < 16; ++k) {
            float v = (row < nr) ? fs[row][part*16 + k] * sw[part*16 + k] : 0.0f;
            s += v * v;
        }
        s += __shfl_xor_sync(0xffffffffu, s, 1);
        s += __shfl_xor_sync(0xffffffffu, s, 2);
        if (part == 0)
            scs[row] = (row < nr) ? 1.0f / fmaxf(sqrtf(s), 1e-12f) : 0.0f;
        if (row >= nr) {
            #pragma unroll
            for (int k = 0; k < 16; ++k) fs[row][part*16 + k] = 0.0f;
        }
    }
    __syncthreads();

    const int half = tid >> 7;       // n parity
    const int lt   = tid & 127;
    const int ty   = lt >> 3;        // j group (0..15), 4 rows
    const int tx   = lt & 7;         // d group (0..7), 8 cols
    float acc[4][8];
    #pragma unroll
    for (int i = 0; i < 4; ++i)
        #pragma unroll
        for (int j = 0; j < 8; ++j) acc[i][j] = 0.0f;
    float ksa[4] = {0.f, 0.f, 0.f, 0.f};

    #pragma unroll 4
    for (int n = half; n < 64; n += 2) {
        const float  sc = scs[n];
        const float4 w4 = *(const float4*)&fs[n][ty*4];
        const float4 fa = *(const float4*)&fs[n][tx*8];
        const float4 fb = *(const float4*)&fs[n][tx*8 + 4];
        const float sv[4] = {sc*w4.x, sc*w4.y, sc*w4.z, sc*w4.w};
        const float fv[8] = {fa.x, fa.y, fa.z, fa.w, fb.x, fb.y, fb.z, fb.w};
        #pragma unroll
        for (int jj = 0; jj < 4; ++jj)
            #pragma unroll
            for (int dd = 0; dd < 8; ++dd)
                acc[jj][dd] += sv[jj] * fv[dd];
        if (tx == 0) {
            ksa[0] += sv[0]; ksa[1] += sv[1]; ksa[2] += sv[2]; ksa[3] += sv[3];
        }
    }

    if (half == 1) {
        #pragma unroll
        for (int jj = 0; jj < 4; ++jj)
            #pragma unroll
            for (int dd = 0; dd < 8; ++dd)
                red[lt][jj*8 + dd] = acc[jj][dd];
        if (tx == 0) {
            #pragma unroll
            for (int jj = 0; jj < 4; ++jj) sks[ty*4 + jj] = ksa[jj];
        }
    }
    __syncthreads();
    if (half == 0) {
        float* Sb = g_S5 + (size_t)blk * Dd * Dd;
        #pragma unroll
        for (int jj = 0; jj < 4; ++jj) {
            float4 lo, hi;
            lo.x = acc[jj][0] + red[lt][jj*8 + 0];
            lo.y = acc[jj][1] + red[lt][jj*8 + 1];
            lo.z = acc[jj][2] + red[lt][jj*8 + 2];
            lo.w = acc[jj][3] + red[lt][jj*8 + 3];
            hi.x = acc[jj][4] + red[lt][jj*8 + 4];
            hi.y = acc[jj][5] + red[lt][jj*8 + 5];
            hi.z = acc[jj][6] + red[lt][jj*8 + 6];
            hi.w = acc[jj][7] + red[lt][jj*8 + 7];
            *(float4*)&Sb[(ty*4 + jj)*Dd + tx*8]     = lo;
            *(float4*)&Sb[(ty*4 + jj)*Dd + tx*8 + 4] = hi;
        }
        if (tx == 0) {
            #pragma unroll
            for (int jj = 0; jj < 4; ++jj)
                g_ss5[blk*Dd + ty*4 + jj] = ksa[jj] + sks[ty*4 + jj];
        }
    }
}

// ---------------------------------------------------------------------------
// Kernel B: per window: Ms[j,:] = sw2[j] * sum of 15 partial S slices;
//   G = Ms @ w1;  v[j] = sw2[j] * sum of 15 partial ss. grid=160, 256 thr.
// ---------------------------------------------------------------------------
__global__ __launch_bounds__(256) void kB(const float* __restrict__ w1,
                                          const float* __restrict__ weights) {
    __shared__ float Ms[Dd*Dd];
    __shared__ float w1s[Dd*Dd];
    __shared__ float sw2[Dd];
    const int bw  = blockIdx.x;
    const int b   = bw / T2;
    const int t2  = bw % T2;
    const int bt0 = b * Tt + t2;
    const int tid = threadIdx.x;

    if (tid < Dd) {
        float s = 1.0f / (1.0f + expf(-weights[tid]));
        sw2[tid] = s * s;
    }
    __syncthreads();

    for (int i = tid; i < 1024; i += 256) {
        float4 m = make_float4(0.f, 0.f, 0.f, 0.f);
        #pragma unroll
        for (int s = 0; s < 3; ++s)
            #pragma unroll
            for (int cc = 0; cc < 5; ++cc) {
                const float4 v = ((const float4*)(g_S5 +
                    (size_t)((bt0 + s)*5 + cc) * Dd * Dd))[i];
                m.x += v.x; m.y += v.y; m.z += v.z; m.w += v.w;
            }
        const float s2 = sw2[i >> 4];
        m.x *= s2; m.y *= s2; m.z *= s2; m.w *= s2;
        ((float4*)Ms)[i]  = m;
        ((float4*)w1s)[i] = ((const float4*)w1)[i];
    }
    if (tid < Dd) {
        float s = 0.0f;
        #pragma unroll
        for (int sl = 0; sl < 15; ++sl)
            s += g_ss5[((bt0 + sl/5)*5 + sl%5)*Dd + tid];
        g_v[bw*Dd + tid] = sw2[tid] * s;
    }
    __syncthreads();

    const int d  = tid & 63;
    const int jg = tid >> 6;
    float* Gb = g_G + (size_t)bw * Dd * Dd;
    for (int j = jg*16; j < jg*16 + 16; ++j) {
        float s = 0.0f;
        #pragma unroll 16
        for (int k = 0; k < 64; ++k)
            s += Ms[j*64 + k] * w1s[k*64 + d];
        Gb[j*64 + d] = s;
    }
}

// ---------------------------------------------------------------------------
// Kernel C: per (window, 64-row tile): u = F@G; deg = F@v;
//   r = relu(u/deg + b1); h = r@w2 + b2; s = F + h; LayerNorm -> out.
// 128 threads, thread tile 4 rows x 8 cols. grid = 800 blocks.
// ---------------------------------------------------------------------------
__global__ __launch_bounds__(128) void kC(const float* __restrict__ feat,
                                          const float* __restrict__ b1,
                                          const float* __restrict__ w2,
                                          const float* __restrict__ b2,
                                          const float* __restrict__ gamma,
                                          const float* __restrict__ beta,
                                          float* __restrict__ out) {
    __shared__ float Gs[Dd*Dd];      // G, later reused for w2
    __shared__ float QR[Dd*QPAD];    // F^T, later reused for R^T
    __shared__ float kss[Dd], b1s[Dd], b2s[Dd], gms[Dd], bts[Dd], degs[64];

    const int blk  = blockIdx.x;
    const int bw   = blk / 5;
    const int tile = blk % 5;
    const int r0   = tile * 64;
    const int nr   = min(64, Nn - r0);
    const int b    = bw / T2;
    const int t2   = bw % T2;
    const int tid  = threadIdx.x;
    const int ty   = tid >> 3;       // row group 0..15 (4 rows each)
    const int tx   = tid & 7;        // col group 0..7  (8 cols each)

    const float* fb = feat + ((size_t)((b*Tt + t2 + 2)*Nn) + r0) * Dd;

    // stage F^T (zero-fill invalid rows), G, small vectors
    {
        const float4* qb = (const float4*)fb;
        for (int idx = tid; idx < 1024; idx += 128) {
            const int row = idx >> 4, c4 = idx & 15;
            float4 v = make_float4(0.f, 0.f, 0.f, 0.f);
            if (row < nr) v = qb[row*16 + c4];
            QR[(c4*4 + 0)*QPAD + row] = v.x;
            QR[(c4*4 + 1)*QPAD + row] = v.y;
            QR[(c4*4 + 2)*QPAD + row] = v.z;
            QR[(c4*4 + 3)*QPAD + row] = v.w;
        }
        const float4* Gb = (const float4*)(g_G + (size_t)bw * Dd * Dd);
        for (int i = tid; i < 1024; i += 128)
            ((float4*)Gs)[i] = Gb[i];
        if (tid < Dd) {
            kss[tid] = g_v[bw*Dd + tid];
            b1s[tid] = b1[tid]; b2s[tid] = b2[tid];
            gms[tid] = gamma[tid]; bts[tid] = beta[tid];
        }
    }
    __syncthreads();

    // deg per row (threads 0..63)
    if (tid < 64) {
        float s = 0.0f;
        #pragma unroll 16
        for (int k = 0; k < 64; ++k)
            s += QR[k*QPAD + tid] * kss[k];
        degs[tid] = (s == 0.0f) ? 0.0f : 1.0f / s;
    }
    __syncthreads();

    // GEMM1: u = F @ G   (thread: 4 rows x 8 cols)
    float acc[4][8];
    #pragma unroll
    for (int i = 0; i < 4; ++i)
        #pragma unroll
        for (int j = 0; j < 8; ++j) acc[i][j] = 0.0f;

    #pragma unroll 8
    for (int k = 0; k < 64; ++k) {
        const float4 a4 = *(const float4*)&QR[k*QPAD + ty*4];
        const float4 ba = *(const float4*)&Gs[k*Dd + tx*8];
        const float4 bb = *(const float4*)&Gs[k*Dd + tx*8 + 4];
        const float av[4] = {a4.x, a4.y, a4.z, a4.w};
        const float bv[8] = {ba.x, ba.y, ba.z, ba.w, bb.x, bb.y, bb.z, bb.w};
        #pragma unroll
        for (int i = 0; i < 4; ++i)
            #pragma unroll
            for (int j = 0; j < 8; ++j)
                acc[i][j] += av[i] * bv[j];
    }

    // relu(u/deg + b1)
    float r[4][8];
    #pragma unroll
    for (int i = 0; i < 4; ++i) {
        const float dinv = degs[ty*4 + i];
        #pragma unroll
        for (int j = 0; j < 8; ++j)
            r[i][j] = fmaxf(acc[i][j] * dinv + b1s[tx*8 + j], 0.0f);
    }
    __syncthreads();   // done reading QR/Gs

    // store R^T into QR, load w2 into Gs
    #pragma unroll
    for (int i = 0; i < 4; ++i)
        #pragma unroll
        for (int j = 0; j < 8; ++j)
            QR[(tx*8 + j)*QPAD + ty*4 + i] = r[i][j];
    {
        const float4* w2b = (const float4*)w2;
        for (int i = tid; i < 1024; i += 128)
            ((float4*)Gs)[i] = w2b[i];
    }
    __syncthreads();

    // GEMM2: h = R @ w2
    #pragma unroll
    for (int i = 0; i < 4; ++i)
        #pragma unroll
        for (int j = 0; j < 8; ++j) acc[i][j] = 0.0f;

    #pragma unroll 8
    for (int k = 0; k < 64; ++k) {
        const float4 a4 = *(const float4*)&QR[k*QPAD + ty*4];
        const float4 ba = *(const float4*)&Gs[k*Dd + tx*8];
        const float4 bb = *(const float4*)&Gs[k*Dd + tx*8 + 4];
        const float av[4] = {a4.x, a4.y, a4.z, a4.w};
        const float bv[8] = {ba.x, ba.y, ba.z, ba.w, bb.x, bb.y, bb.z, bb.w};
        #pragma unroll
        for (int i = 0; i < 4; ++i)
            #pragma unroll
            for (int j = 0; j < 8; ++j)
                acc[i][j] += av[i] * bv[j];
    }

    // epilogue: residual + bias, LayerNorm per row (8 threads/row, width-8 shfl)
    float* ob = out + ((size_t)bw * Nn + r0) * Dd;
    #pragma unroll
    for (int i = 0; i < 4; ++i) {
        const int row = ty*4 + i;
        const bool valid = row < nr;
        float4 fa = make_float4(0.f, 0.f, 0.f, 0.f);
        float4 fv = make_float4(0.f, 0.f, 0.f, 0.f);
        if (valid) {
            fa = ((const float4*)fb)[row*16 + tx*2];
            fv = ((const float4*)fb)[row*16 + tx*2 + 1];
        }
        float h[8];
        h[0] = acc[i][0] + fa.x + b2s[tx*8 + 0];
        h[1] = acc[i][1] + fa.y + b2s[tx*8 + 1];
        h[2] = acc[i][2] + fa.z + b2s[tx*8 + 2];
        h[3] = acc[i][3] + fa.w + b2s[tx*8 + 3];
        h[4] = acc[i][4] + fv.x + b2s[tx*8 + 4];
        h[5] = acc[i][5] + fv.y + b2s[tx*8 + 5];
        h[6] = acc[i][6] + fv.z + b2s[tx*8 + 6];
        h[7] = acc[i][7] + fv.w + b2s[tx*8 + 7];

        float s = 0.0f;
        #pragma unroll
        for (int j = 0; j < 8; ++j) s += h[j];
        #pragma unroll
        for (int m = 1; m < 8; m <<= 1)
            s += __shfl_xor_sync(0xffffffffu, s, m, 8);
        const float mu = s * (1.0f / 64.0f);

        float vs = 0.0f;
        #pragma unroll
        for (int j = 0; j < 8; ++j) { float a = h[j] - mu; vs += a * a; }
        #pragma unroll
        for (int m = 1; m < 8; m <<= 1)
            vs += __shfl_xor_sync(0xffffffffu, vs, m, 8);
        const float rstd = rsqrtf(vs * (1.0f / 64.0f) + 1e-5f);

        if (valid) {
            float4 o0, o1;
            o0.x = (h[0] - mu) * rstd * gms[tx*8 + 0] + bts[tx*8 + 0];
            o0.y = (h[1] - mu) * rstd * gms[tx*8 + 1] + bts[tx*8 + 1];
            o0.z = (h[2] - mu) * rstd * gms[tx*8 + 2] + bts[tx*8 + 2];
            o0.w = (h[3] - mu) * rstd * gms[tx*8 + 3] + bts[tx*8 + 3];
            o1.x = (h[4] - mu) * rstd * gms[tx*8 + 4] + bts[tx*8 + 4];
            o1.y = (h[5] - mu) * rstd * gms[tx*8 + 5] + bts[tx*8 + 5];
            o1.z = (h[6] - mu) * rstd * gms[tx*8 + 6] + bts[tx*8 + 6];
            o1.w = (h[7] - mu) * rstd * gms[tx*8 + 7] + bts[tx*8 + 7];
            ((float4*)ob)[row*16 + tx*2]     = o0;
            ((float4*)ob)[row*16 + tx*2 + 1] = o1;
        }
    }
}

extern "C" void kernel_launch(void* const* d_in, const int* in_sizes, int n_in,
                              void* d_out, int out_size) {
    const float* feat    = (const float*)d_in[0];
    const float* weights = (const float*)d_in[1];
    const float* w1      = (const float*)d_in[2];
    const float* b1      = (const float*)d_in[3];
    const float* w2      = (const float*)d_in[4];
    const float* b2      = (const float*)d_in[5];
    const float* gamma   = (const float*)d_in[6];
    const float* beta    = (const float*)d_in[7];
    float* out = (float*)d_out;

    kA<<<BT*5, 256>>>(feat, weights);
    kB<<<BW, 256>>>(w1, weights);
    kC<<<BW*5, 128>>>(feat, b1, w2, b2, gamma, beta, out);
}

// round 8
// speedup vs baseline: 1.1759x; 1.1759x over previous
#include <cuda_runtime.h>
#include <math.h>

#define Bb 16
#define Tt 12
#define Nn 300
#define Dd 64
#define T2 10
#define BT (Bb*Tt)        // 192
#define BW (Bb*T2)        // 160
#define QPAD 68           // padded row stride (multiple of 4 for float4 LDS)

// Scratch (static device allocations; no cudaMalloc allowed)
__device__ float g_S5[BT*5*Dd*Dd];     // partial S = sum_n sc_n f f^T per (bt,chunk)
__device__ float g_ss5[BT*5*Dd];       // partial ss = sum_n sc_n f[n,:]
__device__ float g_G[BW*Dd*Dd];        // per-window diag(sw^2) S_win w1
__device__ float g_v[BW*Dd];           // per-window sw^2 * ss_win

// ---------------------------------------------------------------------------
// Kernel A: per (bt, chunk of 64 rows): sc_n = 1/max(||f_n .* sw||,eps),
//   partial S[j,d] = sum_n sc_n f[n,j] f[n,d]  (SYMMETRIC -> only upper
//   triangle of 4x4 thread-tiles computed, mirror written), partial ss[j].
// 256 threads: tids 0..135 own the 136 upper-tri tiles (warps 0..4),
// warp 7 lanes 0..15 compute ss. Warps 5,6 idle through the MAC.
// ---------------------------------------------------------------------------
__global__ __launch_bounds__(256) void kA(const float* __restrict__ feat,
                                          const float* __restrict__ weights) {
    __shared__ float sw[Dd];
    __shared__ float fs[64][Dd];
    __shared__ float scs[64];
    const int blk = blockIdx.x;
    const int bt  = blk / 5;
    const int c   = blk % 5;
    const int r0  = c * 64;
    const int nr  = min(64, Nn - r0);     // 64 or 44
    const int tid = threadIdx.x;
    if (tid < Dd) sw[tid] = 1.0f / (1.0f + expf(-weights[tid]));

    const float* fbase = feat + ((size_t)bt * Nn + r0) * Dd;
    const int nv = nr * 16;
    for (int i = tid; i < nv; i += 256)
        ((float4*)fs)[i] = ((const float4*)fbase)[i];
    __syncthreads();

    // per-row scale (4 threads/row)
    {
        const int row = tid >> 2, part = tid & 3;
        float s = 0.0f;
        #pragma unroll
        for (int k = 0; k < 16; ++k) {
            float v = (row < nr) ? fs[row][part*16 + k] * sw[part*16 + k] : 0.0f;
            s += v * v;
        }
        s += __shfl_xor_sync(0xffffffffu, s, 1);
        s += __shfl_xor_sync(0xffffffffu, s, 2);
        if (part == 0)
            scs[row] = (row < nr) ? 1.0f / fmaxf(sqrtf(s), 1e-12f) : 0.0f;
    }
    __syncthreads();

    if (tid < 136) {
        // decode upper-triangular tile (rr <= cc) from linear index
        int t = tid, rr = 0;
        while (t >= 16 - rr) { t -= 16 - rr; ++rr; }
        const int cc = rr + t;

        float acc[4][4];
        #pragma unroll
        for (int i = 0; i < 4; ++i)
            #pragma unroll
            for (int j = 0; j < 4; ++j) acc[i][j] = 0.0f;

        #pragma unroll 4
        for (int n = 0; n < nr; ++n) {
            const float  sc = scs[n];
            const float4 w4 = *(const float4*)&fs[n][rr*4];
            const float4 f4 = *(const float4*)&fs[n][cc*4];
            const float sv[4] = {sc*w4.x, sc*w4.y, sc*w4.z, sc*w4.w};
            const float fv[4] = {f4.x, f4.y, f4.z, f4.w};
            #pragma unroll
            for (int jj = 0; jj < 4; ++jj)
                #pragma unroll
                for (int dd = 0; dd < 4; ++dd)
                    acc[jj][dd] += sv[jj] * fv[dd];
        }

        float* Sb = g_S5 + (size_t)blk * Dd * Dd;
        #pragma unroll
        for (int jj = 0; jj < 4; ++jj)
            *(float4*)&Sb[(rr*4 + jj)*Dd + cc*4] =
                make_float4(acc[jj][0], acc[jj][1], acc[jj][2], acc[jj][3]);
        if (rr != cc) {
            #pragma unroll
            for (int dd = 0; dd < 4; ++dd)
                *(float4*)&Sb[(cc*4 + dd)*Dd + rr*4] =
                    make_float4(acc[0][dd], acc[1][dd], acc[2][dd], acc[3][dd]);
        }
    } else if (tid >= 224 && tid < 240) {
        // warp 7 lanes 0..15: column sums ss[j] = sum_n sc_n f[n,j]
        const int jg = tid - 224;
        float ksa[4] = {0.f, 0.f, 0.f, 0.f};
        #pragma unroll 4
        for (int n = 0; n < nr; ++n) {
            const float  sc = scs[n];
            const float4 w4 = *(const float4*)&fs[n][jg*4];
            ksa[0] += sc*w4.x; ksa[1] += sc*w4.y;
            ksa[2] += sc*w4.z; ksa[3] += sc*w4.w;
        }
        *(float4*)&g_ss5[blk*Dd + jg*4] =
            make_float4(ksa[0], ksa[1], ksa[2], ksa[3]);
    }
}

// ---------------------------------------------------------------------------
// Kernel B: per window: Ms[j,:] = sw2[j] * sum of 15 partial S slices;
//   G = Ms @ w1;  v[j] = sw2[j] * sum of 15 partial ss. grid=160, 256 thr.
// ---------------------------------------------------------------------------
__global__ __launch_bounds__(256) void kB(const float* __restrict__ w1,
                                          const float* __restrict__ weights) {
    __shared__ float Ms[Dd*Dd];
    __shared__ float w1s[Dd*Dd];
    __shared__ float sw2[Dd];
    const int bw  = blockIdx.x;
    const int b   = bw / T2;
    const int t2  = bw % T2;
    const int bt0 = b * Tt + t2;
    const int tid = threadIdx.x;

    if (tid < Dd) {
        float s = 1.0f / (1.0f + expf(-weights[tid]));
        sw2[tid] = s * s;
    }
    __syncthreads();

    for (int i = tid; i < 1024; i += 256) {
        float4 m = make_float4(0.f, 0.f, 0.f, 0.f);
        #pragma unroll
        for (int s = 0; s < 3; ++s)
            #pragma unroll
            for (int cc = 0; cc < 5; ++cc) {
                const float4 v = ((const float4*)(g_S5 +
                    (size_t)((bt0 + s)*5 + cc) * Dd * Dd))[i];
                m.x += v.x; m.y += v.y; m.z += v.z; m.w += v.w;
            }
        const float s2 = sw2[i >> 4];
        m.x *= s2; m.y *= s2; m.z *= s2; m.w *= s2;
        ((float4*)Ms)[i]  = m;
        ((float4*)w1s)[i] = ((const float4*)w1)[i];
    }
    if (tid < Dd) {
        float s = 0.0f;
        #pragma unroll
        for (int sl = 0; sl < 15; ++sl)
            s += g_ss5[((bt0 + sl/5)*5 + sl%5)*Dd + tid];
        g_v[bw*Dd + tid] = sw2[tid] * s;
    }
    __syncthreads();

    const int d  = tid & 63;
    const int jg = tid >> 6;
    float* Gb = g_G + (size_t)bw * Dd * Dd;
    for (int j = jg*16; j < jg*16 + 16; ++j) {
        float s = 0.0f;
        #pragma unroll 16
        for (int k = 0; k < 64; ++k)
            s += Ms[j*64 + k] * w1s[k*64 + d];
        Gb[j*64 + d] = s;
    }
}

// ---------------------------------------------------------------------------
// Kernel C: per (window, 64-row tile): u = F@G; deg = F@v;
//   r = relu(u/deg + b1); h = r@w2 + b2; s = F + h; LayerNorm -> out.
// 256 threads, thread tile 4x4. grid = 800 blocks. (R3-proven config.)
// ---------------------------------------------------------------------------
__global__ __launch_bounds__(256) void kC(const float* __restrict__ feat,
                                          const float* __restrict__ b1,
                                          const float* __restrict__ w2,
                                          const float* __restrict__ b2,
                                          const float* __restrict__ gamma,
                                          const float* __restrict__ beta,
                                          float* __restrict__ out) {
    __shared__ float Gs[Dd*Dd];      // G, later reused for w2
    __shared__ float QR[Dd*QPAD];    // F^T, later reused for R^T
    __shared__ float kss[Dd], b1s[Dd], b2s[Dd], gms[Dd], bts[Dd], degs[64];

    const int blk  = blockIdx.x;
    const int bw   = blk / 5;
    const int tile = blk % 5;
    const int r0   = tile * 64;
    const int nr   = min(64, Nn - r0);
    const int b    = bw / T2;
    const int t2   = bw % T2;
    const int tid  = threadIdx.x;
    const int ty   = tid >> 4;       // row group 0..15
    const int tx   = tid & 15;       // col group 0..15

    const float* fb = feat + ((size_t)((b*Tt + t2 + 2)*Nn) + r0) * Dd;

    // stage F^T (zero-fill invalid rows), G, small vectors
    {
        const float4* qb = (const float4*)fb;
        for (int idx = tid; idx < 1024; idx += 256) {
            const int row = idx >> 4, c4 = idx & 15;
            float4 v = make_float4(0.f, 0.f, 0.f, 0.f);
            if (row < nr) v = qb[row*16 + c4];
            QR[(c4*4 + 0)*QPAD + row] = v.x;
            QR[(c4*4 + 1)*QPAD + row] = v.y;
            QR[(c4*4 + 2)*QPAD + row] = v.z;
            QR[(c4*4 + 3)*QPAD + row] = v.w;
        }
        const float4* Gb = (const float4*)(g_G + (size_t)bw * Dd * Dd);
        for (int i = tid; i < 1024; i += 256)
            ((float4*)Gs)[i] = Gb[i];
        if (tid < Dd) {
            kss[tid] = g_v[bw*Dd + tid];
            b1s[tid] = b1[tid]; b2s[tid] = b2[tid];
            gms[tid] = gamma[tid]; bts[tid] = beta[tid];
        }
    }
    __syncthreads();

    // deg per row (threads 0..63)
    if (tid < 64) {
        float s = 0.0f;
        #pragma unroll 16
        for (int k = 0; k < 64; ++k)
            s += QR[k*QPAD + tid] * kss[k];
        degs[tid] = (s == 0.0f) ? 0.0f : 1.0f / s;
    }
    __syncthreads();

    // GEMM1: u = F @ G
    float acc[4][4];
    #pragma unroll
    for (int i = 0; i < 4; ++i)
        #pragma unroll
        for (int j = 0; j < 4; ++j) acc[i][j] = 0.0f;

    #pragma unroll 8
    for (int k = 0; k < 64; ++k) {
        const float4 a4 = *(const float4*)&QR[k*QPAD + ty*4];
        const float4 b4 = *(const float4*)&Gs[k*Dd + tx*4];
        const float av[4] = {a4.x, a4.y, a4.z, a4.w};
        const float bv[4] = {b4.x, b4.y, b4.z, b4.w};
        #pragma unroll
        for (int i = 0; i < 4; ++i)
            #pragma unroll
            for (int j = 0; j < 4; ++j)
                acc[i][j] += av[i] * bv[j];
    }

    // relu(u/deg + b1) -> registers
    float r[4][4];
    #pragma unroll
    for (int i = 0; i < 4; ++i) {
        const float dinv = degs[ty*4 + i];
        #pragma unroll
        for (int j = 0; j < 4; ++j)
            r[i][j] = fmaxf(acc[i][j] * dinv + b1s[tx*4 + j], 0.0f);
    }
    __syncthreads();   // everyone done reading QR/Gs

    // store R^T into QR, load w2 into Gs
    #pragma unroll
    for (int i = 0; i < 4; ++i)
        #pragma unroll
        for (int j = 0; j < 4; ++j)
            QR[(tx*4 + j)*QPAD + ty*4 + i] = r[i][j];
    {
        const float4* w2b = (const float4*)w2;
        for (int i = tid; i < 1024; i += 256)
            ((float4*)Gs)[i] = w2b[i];
    }
    __syncthreads();

    // GEMM2: h = R @ w2
    #pragma unroll
    for (int i = 0; i < 4; ++i)
        #pragma unroll
        for (int j = 0; j < 4; ++j) acc[i][j] = 0.0f;

    #pragma unroll 8
    for (int k = 0; k < 64; ++k) {
        const float4 a4 = *(const float4*)&QR[k*QPAD + ty*4];
        const float4 b4 = *(const float4*)&Gs[k*Dd + tx*4];
        const float av[4] = {a4.x, a4.y, a4.z, a4.w};
        const float bv[4] = {b4.x, b4.y, b4.z, b4.w};
        #pragma unroll
        for (int i = 0; i < 4; ++i)
            #pragma unroll
            for (int j = 0; j < 4; ++j)
                acc[i][j] += av[i] * bv[j];
    }

    // epilogue: residual + bias, LayerNorm per row (16 threads/row, width-16 shfl)
    float* ob = out + ((size_t)bw * Nn + r0) * Dd;
    #pragma unroll
    for (int i = 0; i < 4; ++i) {
        const int row = ty*4 + i;
        const bool valid = row < nr;
        float4 f4 = make_float4(0.f, 0.f, 0.f, 0.f);
        if (valid) f4 = ((const float4*)fb)[row*16 + tx];
        float h0 = acc[i][0] + f4.x + b2s[tx*4 + 0];
        float h1 = acc[i][1] + f4.y + b2s[tx*4 + 1];
        float h2 = acc[i][2] + f4.z + b2s[tx*4 + 2];
        float h3 = acc[i][3] + f4.w + b2s[tx*4 + 3];

        float s = h0 + h1 + h2 + h3;
        #pragma unroll
        for (int m = 1; m < 16; m <<= 1)
            s += __shfl_xor_sync(0xffffffffu, s, m, 16);
        const float mu = s * (1.0f / 64.0f);

        float a0 = h0 - mu, a1 = h1 - mu, a2 = h2 - mu, a3 = h3 - mu;
        float vs = a0*a0 + a1*a1 + a2*a2 + a3*a3;
        #pragma unroll
        for (int m = 1; m < 16; m <<= 1)
            vs += __shfl_xor_sync(0xffffffffu, vs, m, 16);
        const float rstd = rsqrtf(vs * (1.0f / 64.0f) + 1e-5f);

        if (valid) {
            float4 o;
            o.x = a0 * rstd * gms[tx*4 + 0] + bts[tx*4 + 0];
            o.y = a1 * rstd * gms[tx*4 + 1] + bts[tx*4 + 1];
            o.z = a2 * rstd * gms[tx*4 + 2] + bts[tx*4 + 2];
            o.w = a3 * rstd * gms[tx*4 + 3] + bts[tx*4 + 3];
            ((float4*)ob)[row*16 + tx] = o;
        }
    }
}

extern "C" void kernel_launch(void* const* d_in, const int* in_sizes, int n_in,
                              void* d_out, int out_size) {
    const float* feat    = (const float*)d_in[0];
    const float* weights = (const float*)d_in[1];
    const float* w1      = (const float*)d_in[2];
    const float* b1      = (const float*)d_in[3];
    const float* w2      = (const float*)d_in[4];
    const float* b2      = (const float*)d_in[5];
    const float* gamma   = (const float*)d_in[6];
    const float* beta    = (const float*)d_in[7];
    float* out = (float*)d_out;

    kA<<<BT*5, 256>>>(feat, weights);
    kB<<<BW, 256>>>(w1, weights);
    kC<<<BW*5, 256>>>(feat, b1, w2, b2, gamma, beta, out);
}

// round 9
// speedup vs baseline: 1.2016x; 1.0218x over previous
#include <cuda_runtime.h>
#include <math.h>

#define Bb 16
#define Tt 12
#define Nn 300
#define Dd 64
#define T2 10
#define BT (Bb*Tt)        // 192
#define BW (Bb*T2)        // 160
#define QPAD 68           // padded row stride (multiple of 4 for float4 LDS)

// Scratch (static device allocations; no cudaMalloc allowed)
__device__ float g_S5[BT*5*Dd*Dd];     // partial S = sum_n sc_n f f^T per (bt,chunk)
__device__ float g_ss5[BT*5*Dd];       // partial ss = sum_n sc_n f[n,:]
__device__ float g_G[BW*Dd*Dd];        // per-window diag(sw^2) S_win w1
__device__ float g_v[BW*Dd];           // per-window sw^2 * ss_win

// ---- packed f32x2 helpers (sm_103a) ---------------------------------------
__device__ __forceinline__ unsigned long long pk2(float lo, float hi) {
    unsigned long long r;
    asm("mov.b64 %0, {%1, %2};" : "=l"(r) : "f"(lo), "f"(hi));
    return r;
}
__device__ __forceinline__ void unpk2(unsigned long long v, float& lo, float& hi) {
    asm("mov.b64 {%0, %1}, %2;" : "=f"(lo), "=f"(hi) : "l"(v));
}
__device__ __forceinline__ unsigned long long mul2(unsigned long long a,
                                                   unsigned long long b) {
    unsigned long long r;
    asm("mul.rn.f32x2 %0, %1, %2;" : "=l"(r) : "l"(a), "l"(b));
    return r;
}
__device__ __forceinline__ void fma2(unsigned long long& d,
                                     unsigned long long a,
                                     unsigned long long b) {
    asm("fma.rn.f32x2 %0, %1, %2, %0;" : "+l"(d) : "l"(a), "l"(b));
}

// ---------------------------------------------------------------------------
// Kernel A: per (bt, chunk of 64 rows): sc_n = 1/max(||f_n .* sw||,eps),
//   partial S[j,d] = sum_n sc_n f[n,j] f[n,d]  (symmetric: upper-tri 4x4
//   thread-tiles, mirror written), partial ss[j]. Packed f32x2 MAC.
// ---------------------------------------------------------------------------
__global__ __launch_bounds__(256) void kA(const float* __restrict__ feat,
                                          const float* __restrict__ weights) {
    __shared__ float sw[Dd];
    __shared__ float fs[64][Dd];
    __shared__ float scs[64];
    const int blk = blockIdx.x;
    const int bt  = blk / 5;
    const int c   = blk % 5;
    const int r0  = c * 64;
    const int nr  = min(64, Nn - r0);     // 64 or 44
    const int tid = threadIdx.x;
    if (tid < Dd) sw[tid] = 1.0f / (1.0f + expf(-weights[tid]));

    const float* fbase = feat + ((size_t)bt * Nn + r0) * Dd;
    const int nv = nr * 16;
    for (int i = tid; i < nv; i += 256)
        ((float4*)fs)[i] = ((const float4*)fbase)[i];
    __syncthreads();

    // per-row scale (4 threads/row)
    {
        const int row = tid >> 2, part = tid & 3;
        float s = 0.0f;
        #pragma unroll
        for (int k = 0; k < 16; ++k) {
            float v = (row < nr) ? fs[row][part*16 + k] * sw[part*16 + k] : 0.0f;
            s += v * v;
        }
        s += __shfl_xor_sync(0xffffffffu, s, 1);
        s += __shfl_xor_sync(0xffffffffu, s, 2);
        if (part == 0)
            scs[row] = (row < nr) ? 1.0f / fmaxf(sqrtf(s), 1e-12f) : 0.0f;
    }
    __syncthreads();

    if (tid < 136) {
        // decode upper-triangular tile (rr <= cc) from linear index
        int t = tid, rr = 0;
        while (t >= 16 - rr) { t -= 16 - rr; ++rr; }
        const int cc = rr + t;

        // acc2[p][dd] packs rows (2p, 2p+1) of the 4x4 tile, column dd
        unsigned long long acc2[2][4];
        #pragma unroll
        for (int p = 0; p < 2; ++p)
            #pragma unroll
            for (int d = 0; d < 4; ++d) acc2[p][d] = 0ull;

        #pragma unroll 4
        for (int n = 0; n < nr; ++n) {
            const float  sc = scs[n];
            const float4 w4 = *(const float4*)&fs[n][rr*4];
            const float4 f4 = *(const float4*)&fs[n][cc*4];
            const unsigned long long scp = pk2(sc, sc);
            const unsigned long long sv01 = mul2(scp, pk2(w4.x, w4.y));
            const unsigned long long sv23 = mul2(scp, pk2(w4.z, w4.w));
            const float fv[4] = {f4.x, f4.y, f4.z, f4.w};
            #pragma unroll
            for (int d = 0; d < 4; ++d) {
                const unsigned long long fdd = pk2(fv[d], fv[d]);
                fma2(acc2[0][d], sv01, fdd);
                fma2(acc2[1][d], sv23, fdd);
            }
        }

        float acc[4][4];
        #pragma unroll
        for (int d = 0; d < 4; ++d) {
            unpk2(acc2[0][d], acc[0][d], acc[1][d]);
            unpk2(acc2[1][d], acc[2][d], acc[3][d]);
        }

        float* Sb = g_S5 + (size_t)blk * Dd * Dd;
        #pragma unroll
        for (int jj = 0; jj < 4; ++jj)
            *(float4*)&Sb[(rr*4 + jj)*Dd + cc*4] =
                make_float4(acc[jj][0], acc[jj][1], acc[jj][2], acc[jj][3]);
        if (rr != cc) {
            #pragma unroll
            for (int dd = 0; dd < 4; ++dd)
                *(float4*)&Sb[(cc*4 + dd)*Dd + rr*4] =
                    make_float4(acc[0][dd], acc[1][dd], acc[2][dd], acc[3][dd]);
        }
    } else if (tid >= 224 && tid < 240) {
        // warp 7 lanes 0..15: column sums ss[j] = sum_n sc_n f[n,j]
        const int jg = tid - 224;
        float ksa[4] = {0.f, 0.f, 0.f, 0.f};
        #pragma unroll 4
        for (int n = 0; n < nr; ++n) {
            const float  sc = scs[n];
            const float4 w4 = *(const float4*)&fs[n][jg*4];
            ksa[0] += sc*w4.x; ksa[1] += sc*w4.y;
            ksa[2] += sc*w4.z; ksa[3] += sc*w4.w;
        }
        *(float4*)&g_ss5[blk*Dd + jg*4] =
            make_float4(ksa[0], ksa[1], ksa[2], ksa[3]);
    }
}

// ---------------------------------------------------------------------------
// Kernel B: per window: Ms[j,:] = sw2[j] * sum of 15 partial S slices;
//   G = Ms @ w1;  v[j] = sw2[j] * sum of 15 partial ss. grid=160, 256 thr.
// ---------------------------------------------------------------------------
__global__ __launch_bounds__(256) void kB(const float* __restrict__ w1,
                                          const float* __restrict__ weights) {
    __shared__ float Ms[Dd*Dd];
    __shared__ float w1s[Dd*Dd];
    __shared__ float sw2[Dd];
    const int bw  = blockIdx.x;
    const int b   = bw / T2;
    const int t2  = bw % T2;
    const int bt0 = b * Tt + t2;
    const int tid = threadIdx.x;

    if (tid < Dd) {
        float s = 1.0f / (1.0f + expf(-weights[tid]));
        sw2[tid] = s * s;
    }
    __syncthreads();

    for (int i = tid; i < 1024; i += 256) {
        float4 m = make_float4(0.f, 0.f, 0.f, 0.f);
        #pragma unroll
        for (int s = 0; s < 3; ++s)
            #pragma unroll
            for (int cc = 0; cc < 5; ++cc) {
                const float4 v = ((const float4*)(g_S5 +
                    (size_t)((bt0 + s)*5 + cc) * Dd * Dd))[i];
                m.x += v.x; m.y += v.y; m.z += v.z; m.w += v.w;
            }
        const float s2 = sw2[i >> 4];
        m.x *= s2; m.y *= s2; m.z *= s2; m.w *= s2;
        ((float4*)Ms)[i]  = m;
        ((float4*)w1s)[i] = ((const float4*)w1)[i];
    }
    if (tid < Dd) {
        float s = 0.0f;
        #pragma unroll
        for (int sl = 0; sl < 15; ++sl)
            s += g_ss5[((bt0 + sl/5)*5 + sl%5)*Dd + tid];
        g_v[bw*Dd + tid] = sw2[tid] * s;
    }
    __syncthreads();

    const int d  = tid & 63;
    const int jg = tid >> 6;
    float* Gb = g_G + (size_t)bw * Dd * Dd;
    for (int j = jg*16; j < jg*16 + 16; ++j) {
        float s = 0.0f;
        #pragma unroll 16
        for (int k = 0; k < 64; ++k)
            s += Ms[j*64 + k] * w1s[k*64 + d];
        Gb[j*64 + d] = s;
    }
}

// ---------------------------------------------------------------------------
// Kernel C: per (window, 64-row tile): u = F@G; deg = F@v;
//   r = relu(u/deg + b1); h = r@w2 + b2; s = F + h; LayerNorm -> out.
// 256 threads, thread tile 4x4, packed f32x2 GEMM mainloops. grid = 800.
// ---------------------------------------------------------------------------
__global__ __launch_bounds__(256) void kC(const float* __restrict__ feat,
                                          const float* __restrict__ b1,
                                          const float* __restrict__ w2,
                                          const float* __restrict__ b2,
                                          const float* __restrict__ gamma,
                                          const float* __restrict__ beta,
                                          float* __restrict__ out) {
    __shared__ float Gs[Dd*Dd];      // G, later reused for w2
    __shared__ float QR[Dd*QPAD];    // F^T, later reused for R^T
    __shared__ float kss[Dd], b1s[Dd], b2s[Dd], gms[Dd], bts[Dd], degs[64];

    const int blk  = blockIdx.x;
    const int bw   = blk / 5;
    const int tile = blk % 5;
    const int r0   = tile * 64;
    const int nr   = min(64, Nn - r0);
    const int b    = bw / T2;
    const int t2   = bw % T2;
    const int tid  = threadIdx.x;
    const int ty   = tid >> 4;       // row group 0..15
    const int tx   = tid & 15;       // col group 0..15

    const float* fb = feat + ((size_t)((b*Tt + t2 + 2)*Nn) + r0) * Dd;

    // stage F^T (zero-fill invalid rows), G, small vectors
    {
        const float4* qb = (const float4*)fb;
        for (int idx = tid; idx < 1024; idx += 256) {
            const int row = idx >> 4, c4 = idx & 15;
            float4 v = make_float4(0.f, 0.f, 0.f, 0.f);
            if (row < nr) v = qb[row*16 + c4];
            QR[(c4*4 + 0)*QPAD + row] = v.x;
            QR[(c4*4 + 1)*QPAD + row] = v.y;
            QR[(c4*4 + 2)*QPAD + row] = v.z;
            QR[(c4*4 + 3)*QPAD + row] = v.w;
        }
        const float4* Gb = (const float4*)(g_G + (size_t)bw * Dd * Dd);
        for (int i = tid; i < 1024; i += 256)
            ((float4*)Gs)[i] = Gb[i];
        if (tid < Dd) {
            kss[tid] = g_v[bw*Dd + tid];
            b1s[tid] = b1[tid]; b2s[tid] = b2[tid];
            gms[tid] = gamma[tid]; bts[tid] = beta[tid];
        }
    }
    __syncthreads();

    // deg per row (threads 0..63)
    if (tid < 64) {
        float s = 0.0f;
        #pragma unroll 16
        for (int k = 0; k < 64; ++k)
            s += QR[k*QPAD + tid] * kss[k];
        degs[tid] = (s == 0.0f) ? 0.0f : 1.0f / s;
    }
    __syncthreads();

    // GEMM1: u = F @ G  (packed: acc2[p][j] = rows (2p,2p+1), col j)
    unsigned long long acc2[2][4];
    #pragma unroll
    for (int p = 0; p < 2; ++p)
        #pragma unroll
        for (int j = 0; j < 4; ++j) acc2[p][j] = 0ull;

    #pragma unroll 8
    for (int k = 0; k < 64; ++k) {
        const float4 a4 = *(const float4*)&QR[k*QPAD + ty*4];
        const float4 b4 = *(const float4*)&Gs[k*Dd + tx*4];
        const unsigned long long a01 = pk2(a4.x, a4.y);
        const unsigned long long a23 = pk2(a4.z, a4.w);
        const float bv[4] = {b4.x, b4.y, b4.z, b4.w};
        #pragma unroll
        for (int j = 0; j < 4; ++j) {
            const unsigned long long bb = pk2(bv[j], bv[j]);
            fma2(acc2[0][j], a01, bb);
            fma2(acc2[1][j], a23, bb);
        }
    }

    float acc[4][4];
    #pragma unroll
    for (int j = 0; j < 4; ++j) {
        unpk2(acc2[0][j], acc[0][j], acc[1][j]);
        unpk2(acc2[1][j], acc[2][j], acc[3][j]);
    }

    // relu(u/deg + b1) -> registers
    float r[4][4];
    #pragma unroll
    for (int i = 0; i < 4; ++i) {
        const float dinv = degs[ty*4 + i];
        #pragma unroll
        for (int j = 0; j < 4; ++j)
            r[i][j] = fmaxf(acc[i][j] * dinv + b1s[tx*4 + j], 0.0f);
    }
    __syncthreads();   // everyone done reading QR/Gs

    // store R^T into QR, load w2 into Gs
    #pragma unroll
    for (int i = 0; i < 4; ++i)
        #pragma unroll
        for (int j = 0; j < 4; ++j)
            QR[(tx*4 + j)*QPAD + ty*4 + i] = r[i][j];
    {
        const float4* w2b = (const float4*)w2;
        for (int i = tid; i < 1024; i += 256)
            ((float4*)Gs)[i] = w2b[i];
    }
    __syncthreads();

    // GEMM2: h = R @ w2 (packed)
    #pragma unroll
    for (int p = 0; p < 2; ++p)
        #pragma unroll
        for (int j = 0; j < 4; ++j) acc2[p][j] = 0ull;

    #pragma unroll 8
    for (int k = 0; k < 64; ++k) {
        const float4 a4 = *(const float4*)&QR[k*QPAD + ty*4];
        const float4 b4 = *(const float4*)&Gs[k*Dd + tx*4];
        const unsigned long long a01 = pk2(a4.x, a4.y);
        const unsigned long long a23 = pk2(a4.z, a4.w);
        const float bv[4] = {b4.x, b4.y, b4.z, b4.w};
        #pragma unroll
        for (int j = 0; j < 4; ++j) {
            const unsigned long long bb = pk2(bv[j], bv[j]);
            fma2(acc2[0][j], a01, bb);
            fma2(acc2[1][j], a23, bb);
        }
    }
    #pragma unroll
    for (int j = 0; j < 4; ++j) {
        unpk2(acc2[0][j], acc[0][j], acc[1][j]);
        unpk2(acc2[1][j], acc[2][j], acc[3][j]);
    }

    // epilogue: residual + bias, LayerNorm per row (16 threads/row, width-16 shfl)
    float* ob = out + ((size_t)bw * Nn + r0) * Dd;
    #pragma unroll
    for (int i = 0; i < 4; ++i) {
        const int row = ty*4 + i;
        const bool valid = row < nr;
        float4 f4 = make_float4(0.f, 0.f, 0.f, 0.f);
        if (valid) f4 = ((const float4*)fb)[row*16 + tx];
        float h0 = acc[i][0] + f4.x + b2s[tx*4 + 0];
        float h1 = acc[i][1] + f4.y + b2s[tx*4 + 1];
        float h2 = acc[i][2] + f4.z + b2s[tx*4 + 2];
        float h3 = acc[i][3] + f4.w + b2s[tx*4 + 3];

        float s = h0 + h1 + h2 + h3;
        #pragma unroll
        for (int m = 1; m < 16; m <<= 1)
            s += __shfl_xor_sync(0xffffffffu, s, m, 16);
        const float mu = s * (1.0f / 64.0f);

        float a0 = h0 - mu, a1 = h1 - mu, a2 = h2 - mu, a3 = h3 - mu;
        float vs = a0*a0 + a1*a1 + a2*a2 + a3*a3;
        #pragma unroll
        for (int m = 1; m < 16; m <<= 1)
            vs += __shfl_xor_sync(0xffffffffu, vs, m, 16);
        const float rstd = rsqrtf(vs * (1.0f / 64.0f) + 1e-5f);

        if (valid) {
            float4 o;
            o.x = a0 * rstd * gms[tx*4 + 0] + bts[tx*4 + 0];
            o.y = a1 * rstd * gms[tx*4 + 1] + bts[tx*4 + 1];
            o.z = a2 * rstd * gms[tx*4 + 2] + bts[tx*4 + 2];
            o.w = a3 * rstd * gms[tx*4 + 3] + bts[tx*4 + 3];
            ((float4*)ob)[row*16 + tx] = o;
        }
    }
}

extern "C" void kernel_launch(void* const* d_in, const int* in_sizes, int n_in,
                              void* d_out, int out_size) {
    const float* feat    = (const float*)d_in[0];
    const float* weights = (const float*)d_in[1];
    const float* w1      = (const float*)d_in[2];
    const float* b1      = (const float*)d_in[3];
    const float* w2      = (const float*)d_in[4];
    const float* b2      = (const float*)d_in[5];
    const float* gamma   = (const float*)d_in[6];
    const float* beta    = (const float*)d_in[7];
    float* out = (float*)d_out;

    kA<<<BT*5, 256>>>(feat, weights);
    kB<<<BW, 256>>>(w1, weights);
    kC<<<BW*5, 256>>>(feat, b1, w2, b2, gamma, beta, out);
}

// round 10
// speedup vs baseline: 1.3013x; 1.0830x over previous
#include <cuda_runtime.h>
#include <math.h>

#define Bb 16
#define Tt 12
#define Nn 300
#define Dd 64
#define T2 10
#define BT (Bb*Tt)        // 192
#define BW (Bb*T2)        // 160
#define QPAD 68           // padded row stride (multiple of 4 for float4 LDS)

// Scratch (static device allocations; no cudaMalloc allowed)
__device__ float g_S5[BT*5*Dd*Dd];     // partial S = sum_n sc_n f f^T per (bt,chunk)
__device__ float g_ss5[BT*5*Dd];       // partial ss = sum_n sc_n f[n,:]
__device__ float g_G[BW*Dd*Dd];        // per-window diag(sw^2) S_win w1
__device__ float g_v[BW*Dd];           // per-window sw^2 * ss_win

// ---- packed f32x2 helpers (sm_103a) ---------------------------------------
__device__ __forceinline__ unsigned long long pk2(float lo, float hi) {
    unsigned long long r;
    asm("mov.b64 %0, {%1, %2};" : "=l"(r) : "f"(lo), "f"(hi));
    return r;
}
__device__ __forceinline__ void unpk2(unsigned long long v, float& lo, float& hi) {
    asm("mov.b64 {%0, %1}, %2;" : "=f"(lo), "=f"(hi) : "l"(v));
}
__device__ __forceinline__ unsigned long long mul2(unsigned long long a,
                                                   unsigned long long b) {
    unsigned long long r;
    asm("mul.rn.f32x2 %0, %1, %2;" : "=l"(r) : "l"(a), "l"(b));
    return r;
}
__device__ __forceinline__ void fma2(unsigned long long& d,
                                     unsigned long long a,
                                     unsigned long long b) {
    asm("fma.rn.f32x2 %0, %1, %2, %0;" : "+l"(d) : "l"(a), "l"(b));
}

// ---------------------------------------------------------------------------
// Kernel A: per (bt, chunk of <=64 rows): sc_n = 1/max(||f_n .* sw||,eps),
//   partial S[j,d] = sum_n sc_n f[n,j] f[n,d]  (symmetric: upper-tri 4x4
//   thread-tiles, mirror written), partial ss[j].
// Norm fused into staging (width-16 shfl reduction) -> single barrier.
// ---------------------------------------------------------------------------
__global__ __launch_bounds__(256) void kA(const float* __restrict__ feat,
                                          const float* __restrict__ weights) {
    __shared__ float fs[64][Dd];
    __shared__ float scs[64];
    const int blk = blockIdx.x;
    const int bt  = blk / 5;
    const int c   = blk % 5;
    const int r0  = c * 64;
    const int nr  = min(64, Nn - r0);     // 64 or 44
    const int tid = threadIdx.x;
    const int c4  = tid & 15;             // float4 slot within a row

    // per-thread sigmoid(weights) segment (4 values, registers)
    float4 swv;
    swv.x = 1.0f / (1.0f + expf(-weights[c4*4 + 0]));
    swv.y = 1.0f / (1.0f + expf(-weights[c4*4 + 1]));
    swv.z = 1.0f / (1.0f + expf(-weights[c4*4 + 2]));
    swv.w = 1.0f / (1.0f + expf(-weights[c4*4 + 3]));

    const float* fbase = feat + ((size_t)bt * Nn + r0) * Dd;
    const int nv   = nr * 16;                 // float4 count
    const int trip = ((nv + 255) & ~255);     // uniform trip count for shfl

    // stage + fused weighted-L2 reduction (lanes 0..15 of each half-warp
    // cover one row; width-16 shfl reduces the sum of squares)
    for (int i = tid; i < trip; i += 256) {
        float4 v = make_float4(0.f, 0.f, 0.f, 0.f);
        const bool ok = i < nv;
        if (ok) v = ((const float4*)fbase)[i];
        const float px = v.x*swv.x, py = v.y*swv.y;
        const float pz = v.z*swv.z, pw = v.w*swv.w;
        float ps = px*px + py*py + pz*pz + pw*pw;
        ps += __shfl_xor_sync(0xffffffffu, ps, 1, 16);
        ps += __shfl_xor_sync(0xffffffffu, ps, 2, 16);
        ps += __shfl_xor_sync(0xffffffffu, ps, 4, 16);
        ps += __shfl_xor_sync(0xffffffffu, ps, 8, 16);
        if (ok) {
            ((float4*)fs)[i] = v;
            if (c4 == 0)
                scs[i >> 4] = 1.0f / fmaxf(sqrtf(ps), 1e-12f);
        }
    }
    __syncthreads();

    if (tid < 136) {
        // decode upper-triangular tile (rr <= cc) from linear index
        int t = tid, rr = 0;
        while (t >= 16 - rr) { t -= 16 - rr; ++rr; }
        const int cc = rr + t;

        // acc2[p][dd] packs rows (2p, 2p+1) of the 4x4 tile, column dd
        unsigned long long acc2[2][4];
        #pragma unroll
        for (int p = 0; p < 2; ++p)
            #pragma unroll
            for (int d = 0; d < 4; ++d) acc2[p][d] = 0ull;

        #pragma unroll 8
        for (int n = 0; n < nr; ++n) {
            const float  sc = scs[n];
            const float4 w4 = *(const float4*)&fs[n][rr*4];
            const float4 f4 = *(const float4*)&fs[n][cc*4];
            const unsigned long long scp = pk2(sc, sc);
            const unsigned long long sv01 = mul2(scp, pk2(w4.x, w4.y));
            const unsigned long long sv23 = mul2(scp, pk2(w4.z, w4.w));
            const float fv[4] = {f4.x, f4.y, f4.z, f4.w};
            #pragma unroll
            for (int d = 0; d < 4; ++d) {
                const unsigned long long fdd = pk2(fv[d], fv[d]);
                fma2(acc2[0][d], sv01, fdd);
                fma2(acc2[1][d], sv23, fdd);
            }
        }

        float acc[4][4];
        #pragma unroll
        for (int d = 0; d < 4; ++d) {
            unpk2(acc2[0][d], acc[0][d], acc[1][d]);
            unpk2(acc2[1][d], acc[2][d], acc[3][d]);
        }

        float* Sb = g_S5 + (size_t)blk * Dd * Dd;
        #pragma unroll
        for (int jj = 0; jj < 4; ++jj)
            *(float4*)&Sb[(rr*4 + jj)*Dd + cc*4] =
                make_float4(acc[jj][0], acc[jj][1], acc[jj][2], acc[jj][3]);
        if (rr != cc) {
            #pragma unroll
            for (int dd = 0; dd < 4; ++dd)
                *(float4*)&Sb[(cc*4 + dd)*Dd + rr*4] =
                    make_float4(acc[0][dd], acc[1][dd], acc[2][dd], acc[3][dd]);
        }
    } else if (tid >= 224 && tid < 240) {
        // warp 7 lanes 0..15: column sums ss[j] = sum_n sc_n f[n,j]
        const int jg = tid - 224;
        float ksa[4] = {0.f, 0.f, 0.f, 0.f};
        #pragma unroll 4
        for (int n = 0; n < nr; ++n) {
            const float  sc = scs[n];
            const float4 w4 = *(const float4*)&fs[n][jg*4];
            ksa[0] += sc*w4.x; ksa[1] += sc*w4.y;
            ksa[2] += sc*w4.z; ksa[3] += sc*w4.w;
        }
        *(float4*)&g_ss5[blk*Dd + jg*4] =
            make_float4(ksa[0], ksa[1], ksa[2], ksa[3]);
    }
}

// ---------------------------------------------------------------------------
// Kernel B: per window: Ms[j,:] = sw2[j] * sum of 15 partial S slices;
//   G = Ms @ w1;  v[j] = sw2[j] * sum of 15 partial ss. grid=160, 256 thr.
// ---------------------------------------------------------------------------
__global__ __launch_bounds__(256) void kB(const float* __restrict__ w1,
                                          const float* __restrict__ weights) {
    __shared__ float Ms[Dd*Dd];
    __shared__ float w1s[Dd*Dd];
    __shared__ float sw2[Dd];
    const int bw  = blockIdx.x;
    const int b   = bw / T2;
    const int t2  = bw % T2;
    const int bt0 = b * Tt + t2;
    const int tid = threadIdx.x;

    if (tid < Dd) {
        float s = 1.0f / (1.0f + expf(-weights[tid]));
        sw2[tid] = s * s;
    }
    __syncthreads();

    for (int i = tid; i < 1024; i += 256) {
        float4 m = make_float4(0.f, 0.f, 0.f, 0.f);
        #pragma unroll
        for (int s = 0; s < 3; ++s)
            #pragma unroll
            for (int cc = 0; cc < 5; ++cc) {
                const float4 v = ((const float4*)(g_S5 +
                    (size_t)((bt0 + s)*5 + cc) * Dd * Dd))[i];
                m.x += v.x; m.y += v.y; m.z += v.z; m.w += v.w;
            }
        const float s2 = sw2[i >> 4];
        m.x *= s2; m.y *= s2; m.z *= s2; m.w *= s2;
        ((float4*)Ms)[i]  = m;
        ((float4*)w1s)[i] = ((const float4*)w1)[i];
    }
    if (tid < Dd) {
        float s = 0.0f;
        #pragma unroll
        for (int sl = 0; sl < 15; ++sl)
            s += g_ss5[((bt0 + sl/5)*5 + sl%5)*Dd + tid];
        g_v[bw*Dd + tid] = sw2[tid] * s;
    }
    __syncthreads();

    const int d  = tid & 63;
    const int jg = tid >> 6;
    float* Gb = g_G + (size_t)bw * Dd * Dd;
    for (int j = jg*16; j < jg*16 + 16; ++j) {
        float s = 0.0f;
        #pragma unroll 16
        for (int k = 0; k < 64; ++k)
            s += Ms[j*64 + k] * w1s[k*64 + d];
        Gb[j*64 + d] = s;
    }
}

// ---------------------------------------------------------------------------
// Kernel C: per (window, 64-row tile): u = F@G; deg = F@v (FUSED into GEMM1);
//   r = relu(u/deg + b1); h = r@w2 + b2; s = F + h; LayerNorm -> out.
// 256 threads, 4x4 thread tile, f32x2 mainloops, w2 register prefetch.
// ---------------------------------------------------------------------------
__global__ __launch_bounds__(256) void kC(const float* __restrict__ feat,
                                          const float* __restrict__ b1,
                                          const float* __restrict__ w2,
                                          const float* __restrict__ b2,
                                          const float* __restrict__ gamma,
                                          const float* __restrict__ beta,
                                          float* __restrict__ out) {
    __shared__ float Gs[Dd*Dd];      // G, later reused for w2
    __shared__ float QR[Dd*QPAD];    // F^T, later reused for R^T
    __shared__ float kss[Dd], b1s[Dd], b2s[Dd], gms[Dd], bts[Dd];

    const int blk  = blockIdx.x;
    const int bw   = blk / 5;
    const int tile = blk % 5;
    const int r0   = tile * 64;
    const int nr   = min(64, Nn - r0);
    const int b    = bw / T2;
    const int t2   = bw % T2;
    const int tid  = threadIdx.x;
    const int ty   = tid >> 4;       // row group 0..15
    const int tx   = tid & 15;       // col group 0..15

    const float* fb = feat + ((size_t)((b*Tt + t2 + 2)*Nn) + r0) * Dd;

    // stage F^T (zero-fill invalid rows), G, small vectors
    {
        const float4* qb = (const float4*)fb;
        for (int idx = tid; idx < 1024; idx += 256) {
            const int row = idx >> 4, c4 = idx & 15;
            float4 v = make_float4(0.f, 0.f, 0.f, 0.f);
            if (row < nr) v = qb[row*16 + c4];
            QR[(c4*4 + 0)*QPAD + row] = v.x;
            QR[(c4*4 + 1)*QPAD + row] = v.y;
            QR[(c4*4 + 2)*QPAD + row] = v.z;
            QR[(c4*4 + 3)*QPAD + row] = v.w;
        }
        const float4* Gb = (const float4*)(g_G + (size_t)bw * Dd * Dd);
        for (int i = tid; i < 1024; i += 256)
            ((float4*)Gs)[i] = Gb[i];
        if (tid < Dd) {
            kss[tid] = g_v[bw*Dd + tid];
            b1s[tid] = b1[tid]; b2s[tid] = b2[tid];
            gms[tid] = gamma[tid]; bts[tid] = beta[tid];
        }
    }

    // w2 register prefetch (LDG issued early; consumed after next barrier)
    float4 w2r[4];
    #pragma unroll
    for (int i = 0; i < 4; ++i)
        w2r[i] = ((const float4*)w2)[tid + i*256];

    __syncthreads();

    // GEMM1: u = F @ G, with deg = F @ v fused (per-thread dg for own rows)
    unsigned long long acc2[2][4];
    #pragma unroll
    for (int p = 0; p < 2; ++p)
        #pragma unroll
        for (int j = 0; j < 4; ++j) acc2[p][j] = 0ull;
    unsigned long long dg2[2] = {0ull, 0ull};

    #pragma unroll 8
    for (int k = 0; k < 64; ++k) {
        const float4 a4 = *(const float4*)&QR[k*QPAD + ty*4];
        const float4 b4 = *(const float4*)&Gs[k*Dd + tx*4];
        const float  vk = kss[k];
        const unsigned long long a01 = pk2(a4.x, a4.y);
        const unsigned long long a23 = pk2(a4.z, a4.w);
        const unsigned long long vkk = pk2(vk, vk);
        fma2(dg2[0], a01, vkk);
        fma2(dg2[1], a23, vkk);
        const float bv[4] = {b4.x, b4.y, b4.z, b4.w};
        #pragma unroll
        for (int j = 0; j < 4; ++j) {
            const unsigned long long bb = pk2(bv[j], bv[j]);
            fma2(acc2[0][j], a01, bb);
            fma2(acc2[1][j], a23, bb);
        }
    }

    float acc[4][4], dg[4];
    #pragma unroll
    for (int j = 0; j < 4; ++j) {
        unpk2(acc2[0][j], acc[0][j], acc[1][j]);
        unpk2(acc2[1][j], acc[2][j], acc[3][j]);
    }
    unpk2(dg2[0], dg[0], dg[1]);
    unpk2(dg2[1], dg[2], dg[3]);

    // relu(u/deg + b1) -> registers (deg owned per-thread; no smem phase)
    float r[4][4];
    #pragma unroll
    for (int i = 0; i < 4; ++i) {
        const float dinv = (dg[i] == 0.0f) ? 0.0f : 1.0f / dg[i];
        #pragma unroll
        for (int j = 0; j < 4; ++j)
            r[i][j] = fmaxf(acc[i][j] * dinv + b1s[tx*4 + j], 0.0f);
    }
    __syncthreads();   // everyone done reading QR/Gs

    // store R^T into QR, store prefetched w2 into Gs
    #pragma unroll
    for (int i = 0; i < 4; ++i)
        #pragma unroll
        for (int j = 0; j < 4; ++j)
            QR[(tx*4 + j)*QPAD + ty*4 + i] = r[i][j];
    #pragma unroll
    for (int i = 0; i < 4; ++i)
        ((float4*)Gs)[tid + i*256] = w2r[i];
    __syncthreads();

    // GEMM2: h = R @ w2 (packed)
    #pragma unroll
    for (int p = 0; p < 2; ++p)
        #pragma unroll
        for (int j = 0; j < 4; ++j) acc2[p][j] = 0ull;

    #pragma unroll 8
    for (int k = 0; k < 64; ++k) {
        const float4 a4 = *(const float4*)&QR[k*QPAD + ty*4];
        const float4 b4 = *(const float4*)&Gs[k*Dd + tx*4];
        const unsigned long long a01 = pk2(a4.x, a4.y);
        const unsigned long long a23 = pk2(a4.z, a4.w);
        const float bv[4] = {b4.x, b4.y, b4.z, b4.w};
        #pragma unroll
        for (int j = 0; j < 4; ++j) {
            const unsigned long long bb = pk2(bv[j], bv[j]);
            fma2(acc2[0][j], a01, bb);
            fma2(acc2[1][j], a23, bb);
        }
    }
    #pragma unroll
    for (int j = 0; j < 4; ++j) {
        unpk2(acc2[0][j], acc[0][j], acc[1][j]);
        unpk2(acc2[1][j], acc[2][j], acc[3][j]);
    }

    // epilogue: residual + bias, LayerNorm per row (16 threads/row, width-16 shfl)
    float* ob = out + ((size_t)bw * Nn + r0) * Dd;
    #pragma unroll
    for (int i = 0; i < 4; ++i) {
        const int row = ty*4 + i;
        const bool valid = row < nr;
        float4 f4 = make_float4(0.f, 0.f, 0.f, 0.f);
        if (valid) f4 = ((const float4*)fb)[row*16 + tx];
        float h0 = acc[i][0] + f4.x + b2s[tx*4 + 0];
        float h1 = acc[i][1] + f4.y + b2s[tx*4 + 1];
        float h2 = acc[i][2] + f4.z + b2s[tx*4 + 2];
        float h3 = acc[i][3] + f4.w + b2s[tx*4 + 3];

        float s = h0 + h1 + h2 + h3;
        #pragma unroll
        for (int m = 1; m < 16; m <<= 1)
            s += __shfl_xor_sync(0xffffffffu, s, m, 16);
        const float mu = s * (1.0f / 64.0f);

        float a0 = h0 - mu, a1 = h1 - mu, a2 = h2 - mu, a3 = h3 - mu;
        float vs = a0*a0 + a1*a1 + a2*a2 + a3*a3;
        #pragma unroll
        for (int m = 1; m < 16; m <<= 1)
            vs += __shfl_xor_sync(0xffffffffu, vs, m, 16);
        const float rstd = rsqrtf(vs * (1.0f / 64.0f) + 1e-5f);

        if (valid) {
            float4 o;
            o.x = a0 * rstd * gms[tx*4 + 0] + bts[tx*4 + 0];
            o.y = a1 * rstd * gms[tx*4 + 1] + bts[tx*4 + 1];
            o.z = a2 * rstd * gms[tx*4 + 2] + bts[tx*4 + 2];
            o.w = a3 * rstd * gms[tx*4 + 3] + bts[tx*4 + 3];
            ((float4*)ob)[row*16 + tx] = o;
        }
    }
}

extern "C" void kernel_launch(void* const* d_in, const int* in_sizes, int n_in,
                              void* d_out, int out_size) {
    const float* feat    = (const float*)d_in[0];
    const float* weights = (const float*)d_in[1];
    const float* w1      = (const float*)d_in[2];
    const float* b1      = (const float*)d_in[3];
    const float* w2      = (const float*)d_in[4];
    const float* b2      = (const float*)d_in[5];
    const float* gamma   = (const float*)d_in[6];
    const float* beta    = (const float*)d_in[7];
    float* out = (float*)d_out;

    kA<<<BT*5, 256>>>(feat, weights);
    kB<<<BW, 256>>>(w1, weights);
    kC<<<BW*5, 256>>>(feat, b1, w2, b2, gamma, beta, out);
}